// round 3
// baseline (speedup 1.0000x reference)
#include <cuda_runtime.h>
#include <cuda_bf16.h>
#include <cstdint>
#include <cstddef>

#define BB 32
#define TT 512
#define II 512
#define HH 512
#define EE 4
#define GG 2048
#define KKD 1024
#define OUTD 512
#define NED 8
#define NBLK 128
#define NOUT (BB*TT*OUTD)

// ---------------- device scratch ----------------
__device__ float d_rin[BB*II];
__device__ float d_rh [BB*II];
__device__ int   d_ne[EE];
__device__ int   d_rows[EE][BB];
__device__ int   d_selE[BB][2];
__device__ int   d_selSlot[BB][2];
__device__ float d_selW[BB][2];
__device__ float d_lb_dummy[1];

__device__ float d_Wcat[(size_t)NED*16*KKD*128];     // 64 MB  [ed][jblk][k][c]
__device__ float d_bcat[NED*16*128];
__device__ float d_hstate[2*(size_t)NED*BB*HH];      // parity double-buffer
__device__ float d_hout[(size_t)NED*BB*TT*HH];       // 256 MB slotted outputs
__device__ float d_comb[(size_t)BB*TT*2*HH];         // 64 MB
__device__ unsigned d_sync[NED*32];

__device__ __forceinline__ float fsig(float x)  { return 1.f/(1.f+__expf(-x)); }
__device__ __forceinline__ float ftanh(float x) { float e=__expf(2.f*x); return 1.f - 2.f/(e+1.f); }

// ---------------- prep ----------------
__global__ void k_zero() { d_sync[threadIdx.x] = 0u; }

__global__ void k_wcat(const float* __restrict__ Wih, const float* __restrict__ Whh) {
    int idx = blockIdx.x*256 + threadIdx.x;     // 16,777,216
    int c    = idx & 127;
    int k    = (idx >> 7)  & 1023;
    int jblk = (idx >> 17) & 15;
    int ed   = idx >> 21;
    int g = (c >> 5)*512 + jblk*32 + (c & 31);
    float v;
    if (k < 512) v = __ldg(&Wih[((size_t)(ed*GG + g))*512 + k]);
    else         v = __ldg(&Whh[((size_t)(ed*GG + g))*512 + (k-512)]);
    d_Wcat[idx] = v;
}

__global__ void k_bcat(const float* __restrict__ bih, const float* __restrict__ bhh) {
    int idx = blockIdx.x*256 + threadIdx.x;     // 16384
    int c    = idx & 127;
    int jblk = (idx >> 7) & 15;
    int ed   = idx >> 11;
    int g = (c >> 5)*512 + jblk*32 + (c & 31);
    d_bcat[idx] = bih[ed*GG + g] + bhh[ed*GG + g];
}

// ---------------- router ----------------
__global__ void k_mean(const float* __restrict__ x) {
    int b = blockIdx.x, i = threadIdx.x;
    const float* p = x + (size_t)b*TT*II + i;
    float s = 0.f;
    for (int t = 0; t < TT; ++t) s += p[(size_t)t*II];
    d_rin[b*II + i] = s * (1.f/(float)TT);
}

__global__ void k_rh(const float* __restrict__ rW1, const float* __restrict__ rb1) {
    __shared__ float sr[II];
    int b = blockIdx.x, i = threadIdx.x;
    sr[i] = d_rin[b*II + i];
    __syncthreads();
    float s = rb1[i];
    const float* w = rW1 + (size_t)i*II;
    for (int k = 0; k < II; ++k) s += sr[k]*__ldg(&w[k]);
    d_rh[b*II + i] = s / (1.f + expf(-s));
}

__global__ void k_router2(const float* __restrict__ rW2, const float* __restrict__ rb2,
                          float* __restrict__ lb_out) {
    __shared__ float sl[BB][EE];
    __shared__ float sp[BB][EE];
    int tid = threadIdx.x;
    if (tid < BB*EE) {
        int b = tid >> 2, e = tid & 3;
        float s = rb2[e];
        const float* h = d_rh + b*II;
        const float* w = rW2 + e*II;
        for (int k = 0; k < II; ++k) s += h[k]*__ldg(&w[k]);
        sl[b][e] = s;
    }
    __syncthreads();
    if (tid < BB) {
        int b = tid;
        float m = sl[b][0];
        for (int e = 1; e < EE; ++e) m = fmaxf(m, sl[b][e]);
        float p[EE], sum = 0.f;
        for (int e = 0; e < EE; ++e) { p[e] = expf(sl[b][e]-m); sum += p[e]; }
        for (int e = 0; e < EE; ++e) { p[e] /= sum; sp[b][e] = p[e]; }
        int e0 = 0;
        for (int e = 1; e < EE; ++e) if (p[e] > p[e0]) e0 = e;
        int e1 = -1;
        for (int e = 0; e < EE; ++e) { if (e == e0) continue; if (e1 < 0 || p[e] > p[e1]) e1 = e; }
        float z = p[e0] + p[e1];
        d_selE[b][0] = e0; d_selE[b][1] = e1;
        d_selW[b][0] = p[e0]/z; d_selW[b][1] = p[e1]/z;
    }
    __syncthreads();
    if (tid == 0) {
        for (int e = 0; e < EE; ++e) {
            int nn = 0;
            for (int b = 0; b < BB; ++b)
                for (int k = 0; k < 2; ++k)
                    if (d_selE[b][k] == e) { d_rows[e][nn] = b; d_selSlot[b][k] = nn; nn++; }
            d_ne[e] = nn;
        }
        float lb = 0.f;
        for (int e = 0; e < EE; ++e) {
            float u = 0.f;
            for (int b = 0; b < BB; ++b) u += sp[b][e];
            u *= (1.f/(float)BB);
            float dv = u - 1.f/(float)EE;
            lb += dv*dv;
        }
        *lb_out = 0.01f * lb * (1.f/(float)EE);
    }
}

// ---------------- persistent recurrent kernel ----------------
// dyn smem: As[32][1024] | ws[2][4096] | gs[32*136]
#define SMEM_RECUR ((32*1024 + 2*4096 + 32*136)*4)

__global__ void __launch_bounds__(256,1) k_recur(const float* __restrict__ x) {
    extern __shared__ float sm[];
    float* As = sm;
    float* ws = sm + 32*1024;
    float* gs = ws + 2*4096;
    __shared__ int sRows[BB];
    __shared__ int sN;

    const int tid  = threadIdx.x;
    const int bx   = blockIdx.x;
    const int ed   = bx >> 4;
    const int jblk = bx & 15;
    const int e    = ed >> 1;
    const int dback= ed & 1;
    const int tc = tid & 31, tr = tid >> 5;
    const int c0 = tc*4,     r0 = tr*4;
    const int j0 = jblk*32;

    if (tid < BB) sRows[tid] = d_rows[e][tid];
    if (tid == 0) sN = d_ne[e];
    __syncthreads();
    const int n = sN;
    const bool rowActive = (r0 < n);

    const float4 biasv = *(const float4*)&d_bcat[(ed*16 + jblk)*128 + c0];
    const float* Wblk = d_Wcat + (size_t)(ed*16 + jblk)*(KKD*128);

    const int cr  = tid >> 3;
    const int cj0 = (tid & 7)*4;
    const bool cellActive = (cr < n);
    float creg[4] = {0.f, 0.f, 0.f, 0.f};

    unsigned target = 0;
    for (int s = 0; s < TT; ++s) {
        const int t = dback ? (TT-1-s) : s;

        // ---- stage A = [x_t ; h_prev] (float4) ----
        for (int idx = tid; idx < n*128; idx += 256) {
            int r = idx >> 7, k4 = idx & 127;
            ((float4*)As)[r*256 + k4] =
                __ldg((const float4*)&x[((size_t)(sRows[r]*TT + t))*II + k4*4]);
        }
        if (s == 0) {
            for (int idx = tid; idx < n*128; idx += 256) {
                int r = idx >> 7, k4 = idx & 127;
                ((float4*)As)[r*256 + 128 + k4] = make_float4(0.f,0.f,0.f,0.f);
            }
        } else {
            const float* hsrc = d_hstate + (size_t)((s&1)^1)*(NED*BB*HH) + (size_t)ed*(BB*HH);
            for (int idx = tid; idx < n*128; idx += 256) {
                int r = idx >> 7, k4 = idx & 127;
                ((float4*)As)[r*256 + 128 + k4] = __ldcg((const float4*)&hsrc[r*HH + k4*4]);
            }
        }
        // stage W chunk 0
        {
            const float4* src = (const float4*)Wblk;
            float4* dst = (float4*)ws;
            dst[tid]     = __ldcg(src+tid);     dst[tid+256] = __ldcg(src+tid+256);
            dst[tid+512] = __ldcg(src+tid+512); dst[tid+768] = __ldcg(src+tid+768);
        }
        __syncthreads();

        float acc[4][4];
        #pragma unroll
        for (int i = 0; i < 4; ++i) {
            acc[i][0]=biasv.x; acc[i][1]=biasv.y; acc[i][2]=biasv.z; acc[i][3]=biasv.w;
        }

        int cur = 0;
        #pragma unroll 1
        for (int kc = 0; kc < 32; ++kc) {
            float4 pf0, pf1, pf2, pf3;
            if (kc < 31) {
                const float4* src = (const float4*)(Wblk + (size_t)(kc+1)*4096);
                pf0 = __ldcg(src+tid);     pf1 = __ldcg(src+tid+256);
                pf2 = __ldcg(src+tid+512); pf3 = __ldcg(src+tid+768);
            }
            if (rowActive) {
                const float* wsc = ws + cur*4096;
                #pragma unroll
                for (int kk = 0; kk < 32; kk += 4) {
                    const int kb = kc*32 + kk;
                    float4 a0 = *(const float4*)&As[(r0+0)*1024 + kb];
                    float4 a1 = *(const float4*)&As[(r0+1)*1024 + kb];
                    float4 a2 = *(const float4*)&As[(r0+2)*1024 + kb];
                    float4 a3 = *(const float4*)&As[(r0+3)*1024 + kb];
                    #pragma unroll
                    for (int u = 0; u < 4; ++u) {
                        float4 w = *(const float4*)&wsc[(kk+u)*128 + c0];
                        float av0 = (&a0.x)[u], av1 = (&a1.x)[u], av2 = (&a2.x)[u], av3 = (&a3.x)[u];
                        acc[0][0] += av0*w.x; acc[0][1] += av0*w.y; acc[0][2] += av0*w.z; acc[0][3] += av0*w.w;
                        acc[1][0] += av1*w.x; acc[1][1] += av1*w.y; acc[1][2] += av1*w.z; acc[1][3] += av1*w.w;
                        acc[2][0] += av2*w.x; acc[2][1] += av2*w.y; acc[2][2] += av2*w.z; acc[2][3] += av2*w.w;
                        acc[3][0] += av3*w.x; acc[3][1] += av3*w.y; acc[3][2] += av3*w.z; acc[3][3] += av3*w.w;
                    }
                }
            }
            __syncthreads();
            if (kc < 31) {
                float4* dst = (float4*)(ws + (cur^1)*4096);
                dst[tid] = pf0; dst[tid+256] = pf1; dst[tid+512] = pf2; dst[tid+768] = pf3;
            }
            __syncthreads();
            cur ^= 1;
        }

        // ---- exchange gates ----
        if (rowActive) {
            #pragma unroll
            for (int i = 0; i < 4; ++i)
                *(float4*)&gs[(r0+i)*136 + c0] = make_float4(acc[i][0],acc[i][1],acc[i][2],acc[i][3]);
        }
        __syncthreads();

        // ---- cell update (c in regs) ----
        if (cellActive) {
            float hv[4];
            #pragma unroll
            for (int v = 0; v < 4; ++v) {
                int jj = cj0 + v;
                float ig = fsig (gs[cr*136 +      jj]);
                float fg = fsig (gs[cr*136 + 32 + jj]);
                float gg = ftanh(gs[cr*136 + 64 + jj]);
                float og = fsig (gs[cr*136 + 96 + jj]);
                float c = fg*creg[v] + ig*gg;
                creg[v] = c;
                hv[v] = og * ftanh(c);
            }
            float4 h4 = make_float4(hv[0],hv[1],hv[2],hv[3]);
            __stcg((float4*)&d_hstate[(size_t)(s&1)*(NED*BB*HH) + (size_t)ed*(BB*HH) + cr*HH + j0 + cj0], h4);
            __stcg((float4*)&d_hout[(((size_t)(ed*BB + cr))*TT + t)*HH + j0 + cj0], h4);
        }
        __threadfence();
        __syncthreads();

        // ---- per-(e,d) grid barrier ----
        target += 16;
        if (tid == 0) {
            atomicAdd(&d_sync[ed*32], 1u);
            while (atomicAdd(&d_sync[ed*32], 0u) < target) { __nanosleep(50); }
        }
        __syncthreads();
    }
}

// ---------------- combine ----------------
__global__ void k_combine() {
    int idx = blockIdx.x*256 + threadIdx.x;   // 4,194,304 float4s
    int dj4 = idx & 255;
    int t   = (idx >> 8) & 511;
    int b   = idx >> 17;
    int d   = dj4 >> 7;
    int j4  = dj4 & 127;
    float w0 = d_selW[b][0], w1 = d_selW[b][1];
    int e0 = d_selE[b][0],   e1 = d_selE[b][1];
    int s0 = d_selSlot[b][0], s1 = d_selSlot[b][1];
    float4 h0 = *(const float4*)&d_hout[(((size_t)((e0*2+d)*BB + s0))*TT + t)*HH + j4*4];
    float4 h1 = *(const float4*)&d_hout[(((size_t)((e1*2+d)*BB + s1))*TT + t)*HH + j4*4];
    float4 r;
    r.x = w0*h0.x + w1*h1.x; r.y = w0*h0.y + w1*h1.y;
    r.z = w0*h0.z + w1*h1.z; r.w = w0*h0.w + w1*h1.w;
    ((float4*)d_comb)[idx] = r;
}

// ---------------- out GEMM: [16384,1024] @ [1024,512]^T(row-major Wout[o][k]) ----------------
__global__ void __launch_bounds__(256) k_outgemm(float* __restrict__ out,
                                                 const float* __restrict__ Wout,
                                                 const float* __restrict__ bout) {
    __shared__ float As[16][68];
    __shared__ float Bs[16][68];
    const int tid = threadIdx.x;
    const int m0 = blockIdx.y*64;
    const int n0 = blockIdx.x*64;
    const int tm = tid >> 4, tn = tid & 15;
    float acc[4][4] = {};
    const int r = tid >> 2, q = tid & 3;
    for (int kc = 0; kc < KKD; kc += 16) {
        float4 a = *(const float4*)&d_comb[(size_t)(m0+r)*KKD + kc + q*4];
        As[q*4+0][r]=a.x; As[q*4+1][r]=a.y; As[q*4+2][r]=a.z; As[q*4+3][r]=a.w;
        float4 bb = __ldg((const float4*)&Wout[(size_t)(n0+r)*KKD + kc + q*4]);
        Bs[q*4+0][r]=bb.x; Bs[q*4+1][r]=bb.y; Bs[q*4+2][r]=bb.z; Bs[q*4+3][r]=bb.w;
        __syncthreads();
        #pragma unroll
        for (int k = 0; k < 16; ++k) {
            float4 av = *(const float4*)&As[k][tm*4];
            float4 bv = *(const float4*)&Bs[k][tn*4];
            acc[0][0]+=av.x*bv.x; acc[0][1]+=av.x*bv.y; acc[0][2]+=av.x*bv.z; acc[0][3]+=av.x*bv.w;
            acc[1][0]+=av.y*bv.x; acc[1][1]+=av.y*bv.y; acc[1][2]+=av.y*bv.z; acc[1][3]+=av.y*bv.w;
            acc[2][0]+=av.z*bv.x; acc[2][1]+=av.z*bv.y; acc[2][2]+=av.z*bv.z; acc[2][3]+=av.z*bv.w;
            acc[3][0]+=av.w*bv.x; acc[3][1]+=av.w*bv.y; acc[3][2]+=av.w*bv.z; acc[3][3]+=av.w*bv.w;
        }
        __syncthreads();
    }
    float4 bv = *(const float4*)&bout[n0 + tn*4];
    #pragma unroll
    for (int i = 0; i < 4; ++i) {
        float4 o;
        o.x = acc[i][0]+bv.x; o.y = acc[i][1]+bv.y; o.z = acc[i][2]+bv.z; o.w = acc[i][3]+bv.w;
        *(float4*)&out[(size_t)(m0+tm*4+i)*OUTD + n0 + tn*4] = o;
    }
}

// ---------------- launch ----------------
extern "C" void kernel_launch(void* const* d_in, const int* in_sizes, int n_in,
                              void* d_out, int out_size) {
    const float* x    = (const float*)d_in[0];
    const float* rW1  = (const float*)d_in[1];
    const float* rb1  = (const float*)d_in[2];
    const float* rW2  = (const float*)d_in[3];
    const float* rb2  = (const float*)d_in[4];
    const float* Wih  = (const float*)d_in[5];
    const float* Whh  = (const float*)d_in[6];
    const float* bih  = (const float*)d_in[7];
    const float* bhh  = (const float*)d_in[8];
    const float* Wout = (const float*)d_in[9];
    const float* bout = (const float*)d_in[10];
    float* out = (float*)d_out;

    float* lbdst;
    if (out_size > NOUT) {
        lbdst = out + NOUT;
    } else {
        cudaGetSymbolAddress((void**)&lbdst, d_lb_dummy);
    }

    static bool attrDone = false;
    if (!attrDone) {
        cudaFuncSetAttribute(k_recur, cudaFuncAttributeMaxDynamicSharedMemorySize, SMEM_RECUR);
        attrDone = true;
    }

    k_zero<<<1, NED*32>>>();
    k_wcat<<<65536, 256>>>(Wih, Whh);
    k_bcat<<<64, 256>>>(bih, bhh);
    k_mean<<<BB, II>>>(x);
    k_rh<<<BB, II>>>(rW1, rb1);
    k_router2<<<1, 128>>>(rW2, rb2, lbdst);
    k_recur<<<NBLK, 256, SMEM_RECUR>>>(x);
    k_combine<<<16384, 256>>>();
    dim3 g(OUTD/64, (BB*TT)/64);
    k_outgemm<<<g, 256>>>(out, Wout, bout);
}

// round 4
// speedup vs baseline: 1.0037x; 1.0037x over previous
#include <cuda_runtime.h>
#include <cuda_bf16.h>
#include <cstdint>
#include <cstddef>

#define BB 32
#define TT 512
#define II 512
#define HH 512
#define EE 4
#define GG 2048
#define KKD 1024
#define OUTD 512
#define NED 8
#define NBLK 128
#define NOUT (BB*TT*OUTD)

// ---------------- device scratch ----------------
__device__ float d_rin[BB*II];
__device__ float d_rh [BB*II];
__device__ int   d_ne[EE];
__device__ int   d_rows[EE][BB];
__device__ int   d_selE[BB][2];
__device__ int   d_selSlot[BB][2];
__device__ float d_selW[BB][2];
__device__ float d_lb_dummy[1];

__device__ float d_Wcat[(size_t)NED*16*KKD*128];     // 64 MB  [ed][jblk][k][c]
__device__ float d_bcat[NED*16*128];
__device__ float d_hstate[2*(size_t)NED*BB*HH];      // parity double-buffer
__device__ float d_hout[(size_t)NED*BB*TT*HH];       // 256 MB slotted outputs
__device__ float d_comb[(size_t)BB*TT*2*HH];         // 64 MB
__device__ unsigned d_sync[NED*32];

__device__ __forceinline__ float fsig(float x)  { return 1.f/(1.f+__expf(-x)); }
__device__ __forceinline__ float ftanh(float x) { float e=__expf(2.f*x); return 1.f - 2.f/(e+1.f); }

// ---------------- prep ----------------
__global__ void k_zero() { d_sync[threadIdx.x] = 0u; }

__global__ void k_wcat(const float* __restrict__ Wih, const float* __restrict__ Whh) {
    int idx = blockIdx.x*256 + threadIdx.x;     // 16,777,216
    int c    = idx & 127;
    int k    = (idx >> 7)  & 1023;
    int jblk = (idx >> 17) & 15;
    int ed   = idx >> 21;
    int g = (c >> 5)*512 + jblk*32 + (c & 31);
    float v;
    if (k < 512) v = __ldg(&Wih[((size_t)(ed*GG + g))*512 + k]);
    else         v = __ldg(&Whh[((size_t)(ed*GG + g))*512 + (k-512)]);
    d_Wcat[idx] = v;
}

__global__ void k_bcat(const float* __restrict__ bih, const float* __restrict__ bhh) {
    int idx = blockIdx.x*256 + threadIdx.x;     // 16384
    int c    = idx & 127;
    int jblk = (idx >> 7) & 15;
    int ed   = idx >> 11;
    int g = (c >> 5)*512 + jblk*32 + (c & 31);
    d_bcat[idx] = bih[ed*GG + g] + bhh[ed*GG + g];
}

// ---------------- router ----------------
__global__ void k_mean(const float* __restrict__ x) {
    int b = blockIdx.x, i = threadIdx.x;
    const float* p = x + (size_t)b*TT*II + i;
    float s = 0.f;
    for (int t = 0; t < TT; ++t) s += p[(size_t)t*II];
    d_rin[b*II + i] = s * (1.f/(float)TT);
}

__global__ void k_rh(const float* __restrict__ rW1, const float* __restrict__ rb1) {
    __shared__ float sr[II];
    int b = blockIdx.x, i = threadIdx.x;
    sr[i] = d_rin[b*II + i];
    __syncthreads();
    float s = rb1[i];
    const float* w = rW1 + (size_t)i*II;
    for (int k = 0; k < II; ++k) s += sr[k]*__ldg(&w[k]);
    d_rh[b*II + i] = s / (1.f + expf(-s));
}

__global__ void k_router2(const float* __restrict__ rW2, const float* __restrict__ rb2,
                          float* __restrict__ lb_out) {
    __shared__ float sl[BB][EE];
    __shared__ float sp[BB][EE];
    int tid = threadIdx.x;
    if (tid < BB*EE) {
        int b = tid >> 2, e = tid & 3;
        float s = rb2[e];
        const float* h = d_rh + b*II;
        const float* w = rW2 + e*II;
        for (int k = 0; k < II; ++k) s += h[k]*__ldg(&w[k]);
        sl[b][e] = s;
    }
    __syncthreads();
    if (tid < BB) {
        int b = tid;
        float m = sl[b][0];
        for (int e = 1; e < EE; ++e) m = fmaxf(m, sl[b][e]);
        float p[EE], sum = 0.f;
        for (int e = 0; e < EE; ++e) { p[e] = expf(sl[b][e]-m); sum += p[e]; }
        for (int e = 0; e < EE; ++e) { p[e] /= sum; sp[b][e] = p[e]; }
        int e0 = 0;
        for (int e = 1; e < EE; ++e) if (p[e] > p[e0]) e0 = e;
        int e1 = -1;
        for (int e = 0; e < EE; ++e) { if (e == e0) continue; if (e1 < 0 || p[e] > p[e1]) e1 = e; }
        float z = p[e0] + p[e1];
        d_selE[b][0] = e0; d_selE[b][1] = e1;
        d_selW[b][0] = p[e0]/z; d_selW[b][1] = p[e1]/z;
    }
    __syncthreads();
    if (tid == 0) {
        for (int e = 0; e < EE; ++e) {
            int nn = 0;
            for (int b = 0; b < BB; ++b)
                for (int k = 0; k < 2; ++k)
                    if (d_selE[b][k] == e) { d_rows[e][nn] = b; d_selSlot[b][k] = nn; nn++; }
            d_ne[e] = nn;
        }
        float lb = 0.f;
        for (int e = 0; e < EE; ++e) {
            float u = 0.f;
            for (int b = 0; b < BB; ++b) u += sp[b][e];
            u *= (1.f/(float)BB);
            float dv = u - 1.f/(float)EE;
            lb += dv*dv;
        }
        *lb_out = 0.01f * lb * (1.f/(float)EE);
    }
}

// ---------------- persistent recurrent kernel ----------------
// dyn smem: As[32][1024] | ws[2][4096] | gs[32*136]
#define SMEM_RECUR ((32*1024 + 2*4096 + 32*136)*4)

__global__ void __launch_bounds__(256,1) k_recur(const float* __restrict__ x) {
    extern __shared__ float sm[];
    float* As = sm;
    float* ws = sm + 32*1024;
    float* gs = ws + 2*4096;
    __shared__ int sRows[BB];
    __shared__ int sN;

    const int tid  = threadIdx.x;
    const int bx   = blockIdx.x;
    const int ed   = bx >> 4;
    const int jblk = bx & 15;
    const int e    = ed >> 1;
    const int dback= ed & 1;
    const int tc = tid & 31, tr = tid >> 5;
    const int c0 = tc*4,     r0 = tr*4;
    const int j0 = jblk*32;

    if (tid < BB) sRows[tid] = d_rows[e][tid];
    if (tid == 0) sN = d_ne[e];
    __syncthreads();
    const int n = sN;
    const bool rowActive = (r0 < n);

    const float4 biasv = *(const float4*)&d_bcat[(ed*16 + jblk)*128 + c0];
    const float* Wblk = d_Wcat + (size_t)(ed*16 + jblk)*(KKD*128);

    const int cr  = tid >> 3;
    const int cj0 = (tid & 7)*4;
    const bool cellActive = (cr < n);
    float creg[4] = {0.f, 0.f, 0.f, 0.f};

    unsigned target = 0;
    for (int s = 0; s < TT; ++s) {
        const int t = dback ? (TT-1-s) : s;

        // ---- stage A = [x_t ; h_prev] (float4) ----
        for (int idx = tid; idx < n*128; idx += 256) {
            int r = idx >> 7, k4 = idx & 127;
            ((float4*)As)[r*256 + k4] =
                __ldg((const float4*)&x[((size_t)(sRows[r]*TT + t))*II + k4*4]);
        }
        if (s == 0) {
            for (int idx = tid; idx < n*128; idx += 256) {
                int r = idx >> 7, k4 = idx & 127;
                ((float4*)As)[r*256 + 128 + k4] = make_float4(0.f,0.f,0.f,0.f);
            }
        } else {
            const float* hsrc = d_hstate + (size_t)((s&1)^1)*(NED*BB*HH) + (size_t)ed*(BB*HH);
            for (int idx = tid; idx < n*128; idx += 256) {
                int r = idx >> 7, k4 = idx & 127;
                ((float4*)As)[r*256 + 128 + k4] = __ldcg((const float4*)&hsrc[r*HH + k4*4]);
            }
        }
        // stage W chunk 0
        {
            const float4* src = (const float4*)Wblk;
            float4* dst = (float4*)ws;
            dst[tid]     = __ldcg(src+tid);     dst[tid+256] = __ldcg(src+tid+256);
            dst[tid+512] = __ldcg(src+tid+512); dst[tid+768] = __ldcg(src+tid+768);
        }
        __syncthreads();

        float acc[4][4];
        #pragma unroll
        for (int i = 0; i < 4; ++i) {
            acc[i][0]=biasv.x; acc[i][1]=biasv.y; acc[i][2]=biasv.z; acc[i][3]=biasv.w;
        }

        int cur = 0;
        #pragma unroll 1
        for (int kc = 0; kc < 32; ++kc) {
            float4 pf0, pf1, pf2, pf3;
            if (kc < 31) {
                const float4* src = (const float4*)(Wblk + (size_t)(kc+1)*4096);
                pf0 = __ldcg(src+tid);     pf1 = __ldcg(src+tid+256);
                pf2 = __ldcg(src+tid+512); pf3 = __ldcg(src+tid+768);
            }
            if (rowActive) {
                const float* wsc = ws + cur*4096;
                #pragma unroll
                for (int kk = 0; kk < 32; kk += 4) {
                    const int kb = kc*32 + kk;
                    float4 a0 = *(const float4*)&As[(r0+0)*1024 + kb];
                    float4 a1 = *(const float4*)&As[(r0+1)*1024 + kb];
                    float4 a2 = *(const float4*)&As[(r0+2)*1024 + kb];
                    float4 a3 = *(const float4*)&As[(r0+3)*1024 + kb];
                    #pragma unroll
                    for (int u = 0; u < 4; ++u) {
                        float4 w = *(const float4*)&wsc[(kk+u)*128 + c0];
                        float av0 = (&a0.x)[u], av1 = (&a1.x)[u], av2 = (&a2.x)[u], av3 = (&a3.x)[u];
                        acc[0][0] += av0*w.x; acc[0][1] += av0*w.y; acc[0][2] += av0*w.z; acc[0][3] += av0*w.w;
                        acc[1][0] += av1*w.x; acc[1][1] += av1*w.y; acc[1][2] += av1*w.z; acc[1][3] += av1*w.w;
                        acc[2][0] += av2*w.x; acc[2][1] += av2*w.y; acc[2][2] += av2*w.z; acc[2][3] += av2*w.w;
                        acc[3][0] += av3*w.x; acc[3][1] += av3*w.y; acc[3][2] += av3*w.z; acc[3][3] += av3*w.w;
                    }
                }
            }
            __syncthreads();
            if (kc < 31) {
                float4* dst = (float4*)(ws + (cur^1)*4096);
                dst[tid] = pf0; dst[tid+256] = pf1; dst[tid+512] = pf2; dst[tid+768] = pf3;
            }
            __syncthreads();
            cur ^= 1;
        }

        // ---- exchange gates ----
        if (rowActive) {
            #pragma unroll
            for (int i = 0; i < 4; ++i)
                *(float4*)&gs[(r0+i)*136 + c0] = make_float4(acc[i][0],acc[i][1],acc[i][2],acc[i][3]);
        }
        __syncthreads();

        // ---- cell update (c in regs) ----
        if (cellActive) {
            float hv[4];
            #pragma unroll
            for (int v = 0; v < 4; ++v) {
                int jj = cj0 + v;
                float ig = fsig (gs[cr*136 +      jj]);
                float fg = fsig (gs[cr*136 + 32 + jj]);
                float gg = ftanh(gs[cr*136 + 64 + jj]);
                float og = fsig (gs[cr*136 + 96 + jj]);
                float c = fg*creg[v] + ig*gg;
                creg[v] = c;
                hv[v] = og * ftanh(c);
            }
            float4 h4 = make_float4(hv[0],hv[1],hv[2],hv[3]);
            __stcg((float4*)&d_hstate[(size_t)(s&1)*(NED*BB*HH) + (size_t)ed*(BB*HH) + cr*HH + j0 + cj0], h4);
            __stcg((float4*)&d_hout[(((size_t)(ed*BB + cr))*TT + t)*HH + j0 + cj0], h4);
        }
        __threadfence();
        __syncthreads();

        // ---- per-(e,d) grid barrier ----
        target += 16;
        if (tid == 0) {
            atomicAdd(&d_sync[ed*32], 1u);
            while (atomicAdd(&d_sync[ed*32], 0u) < target) { __nanosleep(50); }
        }
        __syncthreads();
    }
}

// ---------------- combine ----------------
__global__ void k_combine() {
    int idx = blockIdx.x*256 + threadIdx.x;   // 4,194,304 float4s
    int dj4 = idx & 255;
    int t   = (idx >> 8) & 511;
    int b   = idx >> 17;
    int d   = dj4 >> 7;
    int j4  = dj4 & 127;
    float w0 = d_selW[b][0], w1 = d_selW[b][1];
    int e0 = d_selE[b][0],   e1 = d_selE[b][1];
    int s0 = d_selSlot[b][0], s1 = d_selSlot[b][1];
    float4 h0 = *(const float4*)&d_hout[(((size_t)((e0*2+d)*BB + s0))*TT + t)*HH + j4*4];
    float4 h1 = *(const float4*)&d_hout[(((size_t)((e1*2+d)*BB + s1))*TT + t)*HH + j4*4];
    float4 r;
    r.x = w0*h0.x + w1*h1.x; r.y = w0*h0.y + w1*h1.y;
    r.z = w0*h0.z + w1*h1.z; r.w = w0*h0.w + w1*h1.w;
    ((float4*)d_comb)[idx] = r;
}

// ---------------- out GEMM: [16384,1024] @ [1024,512]^T(row-major Wout[o][k]) ----------------
__global__ void __launch_bounds__(256) k_outgemm(float* __restrict__ out,
                                                 const float* __restrict__ Wout,
                                                 const float* __restrict__ bout) {
    __shared__ float As[16][68];
    __shared__ float Bs[16][68];
    const int tid = threadIdx.x;
    const int m0 = blockIdx.y*64;
    const int n0 = blockIdx.x*64;
    const int tm = tid >> 4, tn = tid & 15;
    float acc[4][4] = {};
    const int r = tid >> 2, q = tid & 3;
    for (int kc = 0; kc < KKD; kc += 16) {
        float4 a = *(const float4*)&d_comb[(size_t)(m0+r)*KKD + kc + q*4];
        As[q*4+0][r]=a.x; As[q*4+1][r]=a.y; As[q*4+2][r]=a.z; As[q*4+3][r]=a.w;
        float4 bb = __ldg((const float4*)&Wout[(size_t)(n0+r)*KKD + kc + q*4]);
        Bs[q*4+0][r]=bb.x; Bs[q*4+1][r]=bb.y; Bs[q*4+2][r]=bb.z; Bs[q*4+3][r]=bb.w;
        __syncthreads();
        #pragma unroll
        for (int k = 0; k < 16; ++k) {
            float4 av = *(const float4*)&As[k][tm*4];
            float4 bv = *(const float4*)&Bs[k][tn*4];
            acc[0][0]+=av.x*bv.x; acc[0][1]+=av.x*bv.y; acc[0][2]+=av.x*bv.z; acc[0][3]+=av.x*bv.w;
            acc[1][0]+=av.y*bv.x; acc[1][1]+=av.y*bv.y; acc[1][2]+=av.y*bv.z; acc[1][3]+=av.y*bv.w;
            acc[2][0]+=av.z*bv.x; acc[2][1]+=av.z*bv.y; acc[2][2]+=av.z*bv.z; acc[2][3]+=av.z*bv.w;
            acc[3][0]+=av.w*bv.x; acc[3][1]+=av.w*bv.y; acc[3][2]+=av.w*bv.z; acc[3][3]+=av.w*bv.w;
        }
        __syncthreads();
    }
    float4 bv = *(const float4*)&bout[n0 + tn*4];
    #pragma unroll
    for (int i = 0; i < 4; ++i) {
        float4 o;
        o.x = acc[i][0]+bv.x; o.y = acc[i][1]+bv.y; o.z = acc[i][2]+bv.z; o.w = acc[i][3]+bv.w;
        *(float4*)&out[(size_t)(m0+tm*4+i)*OUTD + n0 + tn*4] = o;
    }
}

// ---------------- launch ----------------
extern "C" void kernel_launch(void* const* d_in, const int* in_sizes, int n_in,
                              void* d_out, int out_size) {
    const float* x    = (const float*)d_in[0];
    const float* rW1  = (const float*)d_in[1];
    const float* rb1  = (const float*)d_in[2];
    const float* rW2  = (const float*)d_in[3];
    const float* rb2  = (const float*)d_in[4];
    const float* Wih  = (const float*)d_in[5];
    const float* Whh  = (const float*)d_in[6];
    const float* bih  = (const float*)d_in[7];
    const float* bhh  = (const float*)d_in[8];
    const float* Wout = (const float*)d_in[9];
    const float* bout = (const float*)d_in[10];
    float* out = (float*)d_out;

    float* lbdst;
    if (out_size > NOUT) {
        lbdst = out + NOUT;
    } else {
        cudaGetSymbolAddress((void**)&lbdst, d_lb_dummy);
    }

    static bool attrDone = false;
    if (!attrDone) {
        cudaFuncSetAttribute(k_recur, cudaFuncAttributeMaxDynamicSharedMemorySize, SMEM_RECUR);
        attrDone = true;
    }

    k_zero<<<1, NED*32>>>();
    k_wcat<<<65536, 256>>>(Wih, Whh);
    k_bcat<<<64, 256>>>(bih, bhh);
    k_mean<<<BB, II>>>(x);
    k_rh<<<BB, II>>>(rW1, rb1);
    k_router2<<<1, 128>>>(rW2, rb2, lbdst);
    k_recur<<<NBLK, 256, SMEM_RECUR>>>(x);
    k_combine<<<16384, 256>>>();
    dim3 g(OUTD/64, (BB*TT)/64);
    k_outgemm<<<g, 256>>>(out, Wout, bout);
}